// round 5
// baseline (speedup 1.0000x reference)
#include <cuda_runtime.h>
#include <cstdint>

// DynamicHead: per-sample grouped 1x1 conv (KERNEL_SIZE=1, PAD=0).
// f:      [B=8, C=400, 128, 128] fp32  (210 MB, read once)
// kernel: [B=8, N=50, 8]         fp32  (12.8 KB)
// out:    [B=8, N=50, 128, 128]  fp32  (26 MB, written once)
//
// R4: 256-bit LDG/STG (sm_100a+ v8.b32) — 1KB contiguous per warp request
// to improve DRAM burst batching. 8 channels processed as 2 groups of 4
// to bound register pressure (~56 regs).

#define N_      50
#define HW_     16384                     // floats per plane
#define HW8_    2048                      // 32B chunks per plane
#define TOTAL8  (8 * 50 * HW8_)           // 819,200 output 32B chunks
#define TPB_    256

__device__ __forceinline__ void ldg256(const float* __restrict__ p, float* v) {
    unsigned r0, r1, r2, r3, r4, r5, r6, r7;
    asm("ld.global.nc.v8.b32 {%0,%1,%2,%3,%4,%5,%6,%7}, [%8];"
        : "=r"(r0), "=r"(r1), "=r"(r2), "=r"(r3),
          "=r"(r4), "=r"(r5), "=r"(r6), "=r"(r7)
        : "l"(p));
    v[0] = __uint_as_float(r0); v[1] = __uint_as_float(r1);
    v[2] = __uint_as_float(r2); v[3] = __uint_as_float(r3);
    v[4] = __uint_as_float(r4); v[5] = __uint_as_float(r5);
    v[6] = __uint_as_float(r6); v[7] = __uint_as_float(r7);
}

__device__ __forceinline__ void stg256(float* p, const float* v) {
    asm volatile("st.global.v8.b32 [%0], {%1,%2,%3,%4,%5,%6,%7,%8};"
        :: "l"(p),
           "r"(__float_as_uint(v[0])), "r"(__float_as_uint(v[1])),
           "r"(__float_as_uint(v[2])), "r"(__float_as_uint(v[3])),
           "r"(__float_as_uint(v[4])), "r"(__float_as_uint(v[5])),
           "r"(__float_as_uint(v[6])), "r"(__float_as_uint(v[7]))
        : "memory");
}

__global__ __launch_bounds__(TPB_)
void dynhead_1x1_v8(const float* __restrict__ f,
                    const float* __restrict__ kern,
                    float* __restrict__ out) {
    const int stride = gridDim.x * TPB_;
    for (int idx = blockIdx.x * TPB_ + threadIdx.x; idx < TOTAL8; idx += stride) {
        const int bn  = idx >> 11;            // / HW8_
        const int pos = idx & (HW8_ - 1);
        const int b = bn / N_;
        const int n = bn - b * N_;

        const float* kp = kern + bn * 8;
        float w0 = __ldg(kp + 0), w1 = __ldg(kp + 1);
        float w2 = __ldg(kp + 2), w3 = __ldg(kp + 3);
        float w4 = __ldg(kp + 4), w5 = __ldg(kp + 5);
        float w6 = __ldg(kp + 6), w7 = __ldg(kp + 7);

        const float* base = f + ((size_t)(b * 400 + n * 8) * HW_ + (pos << 3));

        float va[8], vb[8], vc[8], vd[8], acc[8];

        // Channels 0-3 (4 independent 32B loads in flight)
        ldg256(base + 0 * HW_, va);
        ldg256(base + 1 * HW_, vb);
        ldg256(base + 2 * HW_, vc);
        ldg256(base + 3 * HW_, vd);
#pragma unroll
        for (int j = 0; j < 8; j++) {
            acc[j] = va[j] * w0;
            acc[j] = fmaf(w1, vb[j], acc[j]);
            acc[j] = fmaf(w2, vc[j], acc[j]);
            acc[j] = fmaf(w3, vd[j], acc[j]);
        }

        // Channels 4-7
        ldg256(base + 4 * HW_, va);
        ldg256(base + 5 * HW_, vb);
        ldg256(base + 6 * HW_, vc);
        ldg256(base + 7 * HW_, vd);
#pragma unroll
        for (int j = 0; j < 8; j++) {
            acc[j] = fmaf(w4, va[j], acc[j]);
            acc[j] = fmaf(w5, vb[j], acc[j]);
            acc[j] = fmaf(w6, vc[j], acc[j]);
            acc[j] = fmaf(w7, vd[j], acc[j]);
        }

        stg256(out + ((size_t)idx << 3), acc);
    }
}

extern "C" void kernel_launch(void* const* d_in, const int* in_sizes, int n_in,
                              void* d_out, int out_size) {
    const float* f    = (const float*)d_in[0];
    const float* kern = (const float*)d_in[1];
    float* out        = (float*)d_out;

    int sm = 148;
    cudaDeviceGetAttribute(&sm, cudaDevAttrMultiProcessorCount, 0);
    dim3 grid(sm * 8);   // grid-stride; occupancy self-limits via regs
    dynhead_1x1_v8<<<grid, TPB_>>>(f, kern, out);
}

// round 6
// speedup vs baseline: 1.0444x; 1.0444x over previous
#include <cuda_runtime.h>

// DynamicHead: per-sample grouped 1x1 conv (KERNEL_SIZE=1, PAD=0).
// f:      [B=8, C=400, H=128, W=128] fp32   (210 MB, read exactly once)
// kernel: [B=8, N=50, CPG=8, 1, 1]   fp32   (12.8 KB, L1-resident)
// out:    [B=8, N=50, H=128, W=128]  fp32   (26 MB, written once)
//
// FINAL: pure HBM-bound. Measured ceiling for this read/write streaming mix
// is ~6.18 TB/s regardless of occupancy (64% vs 94%), cache policy
// (default vs .cs), or access width (128b vs 256b) — R2-R4 evidence.
// Best configuration: grid-stride over flattened float4 output, one resident
// wave (SMs x 8 CTAs of 256 thr), 8 independent LDG.128 per output (MLP=8),
// default cache policy.

#define N_      50
#define HW4_    4096                      // 128*128/4 float4 per plane
#define TOTAL4  (8 * 50 * HW4_)           // 1,638,400 output float4
#define TPB_    256

__global__ __launch_bounds__(TPB_)
void dynhead_1x1_gs(const float4* __restrict__ f4,
                    const float* __restrict__ kern,
                    float4* __restrict__ o4) {
    const int stride = gridDim.x * TPB_;
    for (int idx = blockIdx.x * TPB_ + threadIdx.x; idx < TOTAL4; idx += stride) {
        const int bn  = idx >> 12;            // idx / 4096  (0..399)
        const int pos = idx & (HW4_ - 1);
        const int b = bn / N_;                // magic-mul division
        const int n = bn - b * N_;

        // 8 group weights: warp-uniform (whole warp shares bn), L1 broadcast.
        const float* kp = kern + bn * 8;
        float w0 = __ldg(kp + 0), w1 = __ldg(kp + 1);
        float w2 = __ldg(kp + 2), w3 = __ldg(kp + 3);
        float w4 = __ldg(kp + 4), w5 = __ldg(kp + 5);
        float w6 = __ldg(kp + 6), w7 = __ldg(kp + 7);

        // 8 input channel planes for this group; 8 independent LDG.128 (MLP=8).
        const float4* fp = f4 + (((b * 400 + n * 8) << 12) + pos);
        const float4 v0 = fp[0 * HW4_];
        const float4 v1 = fp[1 * HW4_];
        const float4 v2 = fp[2 * HW4_];
        const float4 v3 = fp[3 * HW4_];
        const float4 v4 = fp[4 * HW4_];
        const float4 v5 = fp[5 * HW4_];
        const float4 v6 = fp[6 * HW4_];
        const float4 v7 = fp[7 * HW4_];

        float4 acc;
        acc.x = v0.x * w0; acc.y = v0.y * w0; acc.z = v0.z * w0; acc.w = v0.w * w0;
        acc.x = fmaf(w1, v1.x, acc.x); acc.y = fmaf(w1, v1.y, acc.y);
        acc.z = fmaf(w1, v1.z, acc.z); acc.w = fmaf(w1, v1.w, acc.w);
        acc.x = fmaf(w2, v2.x, acc.x); acc.y = fmaf(w2, v2.y, acc.y);
        acc.z = fmaf(w2, v2.z, acc.z); acc.w = fmaf(w2, v2.w, acc.w);
        acc.x = fmaf(w3, v3.x, acc.x); acc.y = fmaf(w3, v3.y, acc.y);
        acc.z = fmaf(w3, v3.z, acc.z); acc.w = fmaf(w3, v3.w, acc.w);
        acc.x = fmaf(w4, v4.x, acc.x); acc.y = fmaf(w4, v4.y, acc.y);
        acc.z = fmaf(w4, v4.z, acc.z); acc.w = fmaf(w4, v4.w, acc.w);
        acc.x = fmaf(w5, v5.x, acc.x); acc.y = fmaf(w5, v5.y, acc.y);
        acc.z = fmaf(w5, v5.z, acc.z); acc.w = fmaf(w5, v5.w, acc.w);
        acc.x = fmaf(w6, v6.x, acc.x); acc.y = fmaf(w6, v6.y, acc.y);
        acc.z = fmaf(w6, v6.z, acc.z); acc.w = fmaf(w6, v6.w, acc.w);
        acc.x = fmaf(w7, v7.x, acc.x); acc.y = fmaf(w7, v7.y, acc.y);
        acc.z = fmaf(w7, v7.z, acc.z); acc.w = fmaf(w7, v7.w, acc.w);

        o4[idx] = acc;
    }
}

extern "C" void kernel_launch(void* const* d_in, const int* in_sizes, int n_in,
                              void* d_out, int out_size) {
    const float4* f4  = (const float4*)d_in[0];
    const float* kern = (const float*)d_in[1];
    float4* o4        = (float4*)d_out;

    // Exactly one resident wave: 8 CTAs/SM (256 thr -> 2048/SM cap).
    // Host-side attribute query runs at capture time only.
    int sm = 148;
    cudaDeviceGetAttribute(&sm, cudaDevAttrMultiProcessorCount, 0);
    dim3 grid(sm * 8);
    dynhead_1x1_gs<<<grid, TPB_>>>(f4, kern, o4);
}